// round 2
// baseline (speedup 1.0000x reference)
#include <cuda_runtime.h>
#include <math.h>

#define EPSF 1e-6f
#define SCALEF 0.07216878364870323f  // 1/sqrt(192)

// ---------------- device scratch (static, no allocation) ----------------
__device__ float g_qa[32 * 1536];
__device__ float g_kv[32 * 576];
__device__ float g_kvlat[32 * 512];
__device__ float g_kpe[32 * 64];
__device__ float g_q[32 * 24576];
__device__ float g_qeff[32 * 128 * 576];   // [b][h][576] = [q_lat(512) | q_pe(64)]
__device__ float g_scores[32 * 128 * 2048];
__device__ float g_ctx[32 * 128 * 512];
__device__ float g_headout[32 * 16384];

// ---------------- generic M=32 GEMM: C = A(32xK) * B(KxN) ----------------
// grid.x tiles N by 128; grid.y batches (per-head) via element strides.
// 256 threads, each computes 4 rows x 4 cols.
__global__ void gemm32_kernel(const float* __restrict__ A, int lda, int sA,
                              const float* __restrict__ B, int ldb, int sB,
                              float* __restrict__ C, int ldc, int sC,
                              int K, int N) {
    const int y = blockIdx.y;
    A += (long)y * sA;
    B += (long)y * sB;
    C += (long)y * sC;

    __shared__ float As[32][33];
    const int t = threadIdx.x;
    const int tr = t >> 5;          // 0..7  (row group, 4 rows each)
    const int tc = t & 31;          // 0..31 (col group, 4 cols each)
    const int col0 = blockIdx.x * 128 + tc * 4;
    const bool active = (col0 < N);

    float acc[4][4];
#pragma unroll
    for (int i = 0; i < 4; i++)
#pragma unroll
        for (int j = 0; j < 4; j++) acc[i][j] = 0.f;

    for (int k0 = 0; k0 < K; k0 += 32) {
#pragma unroll
        for (int i = 0; i < 4; i++) {
            int e = t + i * 256;
            int r = e >> 5, kk = e & 31;
            As[r][kk] = A[r * lda + k0 + kk];
        }
        __syncthreads();
        if (active) {
#pragma unroll
            for (int kk = 0; kk < 32; kk++) {
                float4 bv = *reinterpret_cast<const float4*>(&B[(long)(k0 + kk) * ldb + col0]);
                float a0 = As[tr * 4 + 0][kk];
                float a1 = As[tr * 4 + 1][kk];
                float a2 = As[tr * 4 + 2][kk];
                float a3 = As[tr * 4 + 3][kk];
                acc[0][0] += a0 * bv.x; acc[0][1] += a0 * bv.y; acc[0][2] += a0 * bv.z; acc[0][3] += a0 * bv.w;
                acc[1][0] += a1 * bv.x; acc[1][1] += a1 * bv.y; acc[1][2] += a1 * bv.z; acc[1][3] += a1 * bv.w;
                acc[2][0] += a2 * bv.x; acc[2][1] += a2 * bv.y; acc[2][2] += a2 * bv.z; acc[2][3] += a2 * bv.w;
                acc[3][0] += a3 * bv.x; acc[3][1] += a3 * bv.y; acc[3][2] += a3 * bv.z; acc[3][3] += a3 * bv.w;
            }
        }
        __syncthreads();
    }
    if (active) {
#pragma unroll
        for (int i = 0; i < 4; i++) {
            float4 v = make_float4(acc[i][0], acc[i][1], acc[i][2], acc[i][3]);
            *reinterpret_cast<float4*>(&C[(long)(tr * 4 + i) * ldc + col0]) = v;
        }
    }
}

// ---------------- rmsnorm(q_a), rmsnorm(kv[:512]), rope(kv[512:576]) ------
__global__ void norm_rope_kernel(float* __restrict__ qa_io,
                                 const float* __restrict__ kv_in,
                                 float* __restrict__ kvlat,
                                 float* __restrict__ kpe,
                                 const float* __restrict__ q_ln_w,
                                 const float* __restrict__ kv_ln_w,
                                 const float* __restrict__ cosd,
                                 const float* __restrict__ sind) {
    const int b = blockIdx.x;
    const int t = threadIdx.x;
    __shared__ float sd[256];

    float* qa = qa_io + b * 1536;
    float ss = 0.f;
    for (int i = t; i < 1536; i += 256) { float v = qa[i]; ss += v * v; }
    sd[t] = ss; __syncthreads();
    for (int o = 128; o > 0; o >>= 1) { if (t < o) sd[t] += sd[t + o]; __syncthreads(); }
    float r = rsqrtf(sd[0] / 1536.f + EPSF);
    __syncthreads();
    for (int i = t; i < 1536; i += 256) qa[i] = qa[i] * r * q_ln_w[i];

    const float* kv = kv_in + b * 576;
    ss = 0.f;
    for (int i = t; i < 512; i += 256) { float v = kv[i]; ss += v * v; }
    sd[t] = ss; __syncthreads();
    for (int o = 128; o > 0; o >>= 1) { if (t < o) sd[t] += sd[t + o]; __syncthreads(); }
    float r2 = rsqrtf(sd[0] / 512.f + EPSF);
    __syncthreads();
    for (int i = t; i < 512; i += 256) kvlat[b * 512 + i] = kv[i] * r2 * kv_ln_w[i];

    if (t < 32) {
        float x1 = kv[512 + 2 * t], x2 = kv[512 + 2 * t + 1];
        float c = cosd[b * 32 + t], s = sind[b * 32 + t];
        kpe[b * 64 + 2 * t]     = x1 * c - x2 * s;
        kpe[b * 64 + 2 * t + 1] = x2 * c + x1 * s;
    }
}

// ---------------- rope q_pe into g_qeff[...,512:576] ----------------
__global__ void qpe_rope_kernel(const float* __restrict__ q,
                                const float* __restrict__ cosd,
                                const float* __restrict__ sind,
                                float* __restrict__ qeff) {
    int idx = blockIdx.x * 256 + threadIdx.x;  // 4096 = 32*128
    int b = idx >> 7, h = idx & 127;
    const float* src = q + b * 24576 + h * 192 + 128;
    float* dst = qeff + (long)(b * 128 + h) * 576 + 512;
#pragma unroll
    for (int i = 0; i < 32; i++) {
        float x1 = src[2 * i], x2 = src[2 * i + 1];
        float c = cosd[b * 32 + i], s = sind[b * 32 + i];
        dst[2 * i]     = x1 * c - x2 * s;
        dst[2 * i + 1] = x2 * c + x1 * s;
    }
}

// ---------------- key fetch with new-token override ----------------
__device__ __forceinline__ float key_elem(int b, int s, int k,
                                          const float* __restrict__ cache_kv,
                                          const float* __restrict__ cache_pe,
                                          const float* __restrict__ kvlat,
                                          const float* __restrict__ kpe,
                                          const int* __restrict__ block_table,
                                          int slotm) {
    int blkid = block_table[b * 16 + (s >> 7)];
    int slot = blkid * 128 + (s & 127);
    if (slot == slotm) {
        return (k < 512) ? kvlat[b * 512 + k] : kpe[b * 64 + (k - 512)];
    }
    return (k < 512) ? cache_kv[(long)slot * 512 + k]
                     : cache_pe[(long)slot * 64 + (k - 512)];
}

// ---------------- scores: per b, (128 heads x 2048 tokens), K=576 ----------
// grid: (32 token tiles, 2 head tiles, 32 batch). 64x64 tile, BK=16, 4x4/thread.
__global__ void scores_kernel(const float* __restrict__ qeff,
                              const float* __restrict__ kvlat,
                              const float* __restrict__ kpe,
                              const float* __restrict__ cache_kv,
                              const float* __restrict__ cache_pe,
                              const int* __restrict__ block_table,
                              const int* __restrict__ slot_mapping,
                              float* __restrict__ scores) {
    const int b = blockIdx.z, mt = blockIdx.y, nt = blockIdx.x;
    const int t = threadIdx.x;
    __shared__ float As[64][17];
    __shared__ float Bs[64][17];
    const int slotm = slot_mapping[b];
    const float* Ab = qeff + (long)b * 73728 + mt * 64 * 576;

    float acc[4][4];
#pragma unroll
    for (int i = 0; i < 4; i++)
#pragma unroll
        for (int j = 0; j < 4; j++) acc[i][j] = 0.f;

    const int tr = t >> 4, tc = t & 15;

    for (int k0 = 0; k0 < 576; k0 += 16) {
#pragma unroll
        for (int i = 0; i < 4; i++) {
            int e = t + i * 256;
            int h = e >> 4, kk = e & 15;
            As[h][kk] = Ab[h * 576 + k0 + kk];
        }
#pragma unroll
        for (int i = 0; i < 4; i++) {
            int e = t + i * 256;
            int sl = e >> 4, kk = e & 15;
            int s = nt * 64 + sl;
            Bs[sl][kk] = key_elem(b, s, k0 + kk, cache_kv, cache_pe, kvlat, kpe,
                                  block_table, slotm);
        }
        __syncthreads();
#pragma unroll
        for (int kk = 0; kk < 16; kk++) {
            float a0 = As[tr * 4 + 0][kk], a1 = As[tr * 4 + 1][kk];
            float a2 = As[tr * 4 + 2][kk], a3 = As[tr * 4 + 3][kk];
            float b0 = Bs[tc * 4 + 0][kk], b1 = Bs[tc * 4 + 1][kk];
            float b2 = Bs[tc * 4 + 2][kk], b3 = Bs[tc * 4 + 3][kk];
            acc[0][0] += a0 * b0; acc[0][1] += a0 * b1; acc[0][2] += a0 * b2; acc[0][3] += a0 * b3;
            acc[1][0] += a1 * b0; acc[1][1] += a1 * b1; acc[1][2] += a1 * b2; acc[1][3] += a1 * b3;
            acc[2][0] += a2 * b0; acc[2][1] += a2 * b1; acc[2][2] += a2 * b2; acc[2][3] += a2 * b3;
            acc[3][0] += a3 * b0; acc[3][1] += a3 * b1; acc[3][2] += a3 * b2; acc[3][3] += a3 * b3;
        }
        __syncthreads();
    }
#pragma unroll
    for (int i = 0; i < 4; i++) {
        float4 v = make_float4(acc[i][0] * SCALEF, acc[i][1] * SCALEF,
                               acc[i][2] * SCALEF, acc[i][3] * SCALEF);
        long row = b * 128 + mt * 64 + tr * 4 + i;
        *reinterpret_cast<float4*>(&scores[row * 2048 + nt * 64 + tc * 4]) = v;
    }
}

// ---------------- softmax per (b,h) row over 2048 with masking -------------
__global__ void softmax_kernel(float* __restrict__ scores,
                               const int* __restrict__ seq_lens) {
    const int row = blockIdx.x;
    const int b = row >> 7;
    const int L = seq_lens[b];
    float* p = scores + (long)row * 2048;
    const int t = threadIdx.x;
    __shared__ float sd[256];

    float m = -1e30f;
    for (int s = t; s < 2048; s += 256)
        if (s < L) m = fmaxf(m, p[s]);
    sd[t] = m; __syncthreads();
    for (int o = 128; o > 0; o >>= 1) { if (t < o) sd[t] = fmaxf(sd[t], sd[t + o]); __syncthreads(); }
    m = sd[0]; __syncthreads();

    float sum = 0.f;
    for (int s = t; s < 2048; s += 256) {
        float e = (s < L) ? __expf(p[s] - m) : 0.f;
        p[s] = e;
        sum += e;
    }
    sd[t] = sum; __syncthreads();
    for (int o = 128; o > 0; o >>= 1) { if (t < o) sd[t] += sd[t + o]; __syncthreads(); }
    float inv = 1.f / sd[0];
    for (int s = t; s < 2048; s += 256) p[s] *= inv;
}

// ---------------- ctx: per b, attn(128x2048) @ keys(2048x512) ---------------
// grid: (8 n tiles, 2 head tiles, 32 batch). 64x64 tile, BK=16.
__global__ void ctx_kernel(const float* __restrict__ scores,
                           const float* __restrict__ kvlat,
                           const float* __restrict__ cache_kv,
                           const int* __restrict__ block_table,
                           const int* __restrict__ slot_mapping,
                           float* __restrict__ ctx) {
    const int b = blockIdx.z, mt = blockIdx.y, nt = blockIdx.x;
    const int t = threadIdx.x;
    __shared__ float As[64][17];
    __shared__ float Bs[16][68];
    const int slotm = slot_mapping[b];

    float acc[4][4];
#pragma unroll
    for (int i = 0; i < 4; i++)
#pragma unroll
        for (int j = 0; j < 4; j++) acc[i][j] = 0.f;

    const int tr = t >> 4, tc = t & 15;

    for (int k0 = 0; k0 < 2048; k0 += 16) {
#pragma unroll
        for (int i = 0; i < 4; i++) {
            int e = t + i * 256;
            int h = e >> 4, kk = e & 15;
            As[h][kk] = scores[(long)(b * 128 + mt * 64 + h) * 2048 + k0 + kk];
        }
#pragma unroll
        for (int i = 0; i < 4; i++) {
            int e = t + i * 256;
            int kk = e >> 6, n = e & 63;
            int s = k0 + kk;
            int blkid = block_table[b * 16 + (s >> 7)];
            int slot = blkid * 128 + (s & 127);
            float v;
            if (slot == slotm) v = kvlat[b * 512 + nt * 64 + n];
            else               v = cache_kv[(long)slot * 512 + nt * 64 + n];
            Bs[kk][n] = v;
        }
        __syncthreads();
#pragma unroll
        for (int kk = 0; kk < 16; kk++) {
            float a0 = As[tr * 4 + 0][kk], a1 = As[tr * 4 + 1][kk];
            float a2 = As[tr * 4 + 2][kk], a3 = As[tr * 4 + 3][kk];
            float b0 = Bs[kk][tc * 4 + 0], b1 = Bs[kk][tc * 4 + 1];
            float b2 = Bs[kk][tc * 4 + 2], b3 = Bs[kk][tc * 4 + 3];
            acc[0][0] += a0 * b0; acc[0][1] += a0 * b1; acc[0][2] += a0 * b2; acc[0][3] += a0 * b3;
            acc[1][0] += a1 * b0; acc[1][1] += a1 * b1; acc[1][2] += a1 * b2; acc[1][3] += a1 * b3;
            acc[2][0] += a2 * b0; acc[2][1] += a2 * b1; acc[2][2] += a2 * b2; acc[2][3] += a2 * b3;
            acc[3][0] += a3 * b0; acc[3][1] += a3 * b1; acc[3][2] += a3 * b2; acc[3][3] += a3 * b3;
        }
        __syncthreads();
    }
#pragma unroll
    for (int i = 0; i < 4; i++) {
        float4 v = make_float4(acc[i][0], acc[i][1], acc[i][2], acc[i][3]);
        long row = b * 128 + mt * 64 + tr * 4 + i;
        *reinterpret_cast<float4*>(&ctx[row * 512 + nt * 64 + tc * 4]) = v;
    }
}

// ------------------------------ host driver ------------------------------
extern "C" void kernel_launch(void* const* d_in, const int* in_sizes, int n_in,
                              void* d_out, int out_size) {
    const float* hidden    = (const float*)d_in[0];
    const float* cosd      = (const float*)d_in[1];
    const float* sind      = (const float*)d_in[2];
    const float* Wq_a      = (const float*)d_in[3];
    const float* q_ln_w    = (const float*)d_in[4];
    const float* Wq_b      = (const float*)d_in[5];
    const float* Wkv_a     = (const float*)d_in[6];
    const float* kv_ln_w   = (const float*)d_in[7];
    const float* Wukt      = (const float*)d_in[8];
    const float* Wuv       = (const float*)d_in[9];
    const float* Wo        = (const float*)d_in[10];
    const float* cache_kv  = (const float*)d_in[11];
    const float* cache_pe  = (const float*)d_in[12];
    const int*   block_tab = (const int*)d_in[13];
    const int*   slot_map  = (const int*)d_in[14];
    const int*   seq_lens  = (const int*)d_in[15];
    float* out = (float*)d_out;

    float *qa, *kvb, *kvlat, *kpe, *q, *qeff, *scores, *ctx, *headout;
    cudaGetSymbolAddress((void**)&qa,      g_qa);
    cudaGetSymbolAddress((void**)&kvb,     g_kv);
    cudaGetSymbolAddress((void**)&kvlat,   g_kvlat);
    cudaGetSymbolAddress((void**)&kpe,     g_kpe);
    cudaGetSymbolAddress((void**)&q,       g_q);
    cudaGetSymbolAddress((void**)&qeff,    g_qeff);
    cudaGetSymbolAddress((void**)&scores,  g_scores);
    cudaGetSymbolAddress((void**)&ctx,     g_ctx);
    cudaGetSymbolAddress((void**)&headout, g_headout);

    // 1) q_a = hidden @ Wq_a   (32x5120 @ 5120x1536)
    gemm32_kernel<<<dim3(12, 1), 256>>>(hidden, 5120, 0, Wq_a, 1536, 0,
                                        qa, 1536, 0, 5120, 1536);
    // 2) kv = hidden @ Wkv_a   (32x5120 @ 5120x576)
    gemm32_kernel<<<dim3(5, 1), 256>>>(hidden, 5120, 0, Wkv_a, 576, 0,
                                       kvb, 576, 0, 5120, 576);
    // 3) rmsnorm(q_a), rmsnorm(kv_lat), rope(k_pe)
    norm_rope_kernel<<<32, 256>>>(qa, kvb, kvlat, kpe, q_ln_w, kv_ln_w, cosd, sind);
    // 4) q = q_a_norm @ Wq_b   (32x1536 @ 1536x24576)
    gemm32_kernel<<<dim3(192, 1), 256>>>(qa, 1536, 0, Wq_b, 24576, 0,
                                         q, 24576, 0, 1536, 24576);
    // 5) rope q_pe -> qeff[..., 512:576]
    qpe_rope_kernel<<<16, 256>>>(q, cosd, sind, qeff);
    // 6) q_lat[b,h,:512] = q_nope[b,h,:] @ W_UK_T[h]  (per-head GEMM, M=32,K=128,N=512)
    gemm32_kernel<<<dim3(4, 128), 256>>>(q, 24576, 192, Wukt, 512, 65536,
                                         qeff, 73728, 576, 128, 512);
    // 7) attention scores
    scores_kernel<<<dim3(32, 2, 32), 256>>>(qeff, kvlat, kpe, cache_kv, cache_pe,
                                            block_tab, slot_map, scores);
    // 8) softmax
    softmax_kernel<<<4096, 256>>>(scores, seq_lens);
    // 9) ctx = attn @ keys
    ctx_kernel<<<dim3(8, 2, 32), 256>>>(scores, kvlat, cache_kv, block_tab,
                                        slot_map, ctx);
    // 10) headout[b, h*128:(h+1)*128] = ctx[b,h,:] @ W_UV[h]  (M=32,K=512,N=128)
    gemm32_kernel<<<dim3(1, 128), 256>>>(ctx, 65536, 512, Wuv, 128, 65536,
                                         headout, 16384, 128, 512, 128);
    // 11) out = headout @ Wo   (32x16384 @ 16384x5120)
    gemm32_kernel<<<dim3(40, 1), 256>>>(headout, 16384, 0, Wo, 5120, 0,
                                        out, 5120, 0, 16384, 5120);
}

// round 3
// speedup vs baseline: 6.5417x; 6.5417x over previous
#include <cuda_runtime.h>
#include <math.h>

#define EPSF 1e-6f
#define SCALEF 0.07216878364870323f  // 1/sqrt(192)

// ---------------- device scratch ----------------
__device__ float g_qa[32 * 1536];
__device__ float g_kv[32 * 576];
__device__ float g_kvlat[32 * 512];
__device__ float g_kpe[32 * 64];
__device__ float g_q[32 * 24576];
__device__ float g_qeff[32 * 128 * 576];   // [b][h][576] = [q_lat(512) | q_pe(64)]
__device__ float g_scores[32 * 128 * 2048];
__device__ float g_ctx[32 * 128 * 512];
__device__ float g_headout[32 * 16384];
__device__ float g_part[8 * 1024 * 1024];  // split-K partials (32 MB)

// =====================================================================
// small-M GEMM: C(32xN) = A(32xK) @ B(KxN); 128 threads, tile 32xBN,
// BK=32, per-thread 8 x (BN/32). Split-K via grid.y (kchunk), batch via
// grid.z (strides sA/sB/sC). If partStride>0, C is a partial buffer.
// =====================================================================
template <int BN>
__global__ __launch_bounds__(128) void smallgemm8(
    const float* __restrict__ A, int lda, long sA,
    const float* __restrict__ B, int ldb, long sB,
    float* __restrict__ C, int ldc, long sC,
    long partStride, int K, int N, int kchunk)
{
    constexpr int CN = BN / 32;       // cols per thread (8 or 4)
    __shared__ float As[32][36];      // [m][kk]
    __shared__ float Bs[32][BN];      // [kk][n]

    const int t = threadIdx.x;
    const int tr = t >> 5;            // 0..3 -> rows tr*8..tr*8+7
    const int tc = t & 31;            // cols tc*CN..
    const int col0 = blockIdx.x * BN;
    const int k0b = blockIdx.y * kchunk;
    const int kend = min(K, k0b + kchunk);

    A += (long)blockIdx.z * sA;
    B += (long)blockIdx.z * sB;
    C += (long)blockIdx.z * sC + (long)blockIdx.y * partStride;

    float acc[8][CN];
#pragma unroll
    for (int i = 0; i < 8; i++)
#pragma unroll
        for (int j = 0; j < CN; j++) acc[i][j] = 0.f;

    for (int k0 = k0b; k0 < kend; k0 += 32) {
        // stage A: 32x32, 2 float4 per thread
#pragma unroll
        for (int i = 0; i < 2; i++) {
            int e = t + i * 128;
            int m = e >> 3, kk0 = (e & 7) * 4;
            float4 v = *reinterpret_cast<const float4*>(&A[(long)m * lda + k0 + kk0]);
            *reinterpret_cast<float4*>(&As[m][kk0]) = v;
        }
        // stage B: 32xBN, BN/16 float4 per thread (guarded by N)
#pragma unroll
        for (int i = 0; i < BN / 16; i++) {
            int e = t + i * 128;
            int kk = e / (BN / 4);
            int n0 = (e % (BN / 4)) * 4;
            float4 v = make_float4(0.f, 0.f, 0.f, 0.f);
            if (col0 + n0 < N)
                v = *reinterpret_cast<const float4*>(&B[(long)(k0 + kk) * ldb + col0 + n0]);
            *reinterpret_cast<float4*>(&Bs[kk][n0]) = v;
        }
        __syncthreads();
#pragma unroll
        for (int kk = 0; kk < 32; kk++) {
            float a[8];
#pragma unroll
            for (int i = 0; i < 8; i++) a[i] = As[tr * 8 + i][kk];
            float bfr[CN];
#pragma unroll
            for (int j4 = 0; j4 < CN / 4; j4++)
                *reinterpret_cast<float4*>(&bfr[j4 * 4]) =
                    *reinterpret_cast<const float4*>(&Bs[kk][tc * CN + j4 * 4]);
#pragma unroll
            for (int i = 0; i < 8; i++)
#pragma unroll
                for (int j = 0; j < CN; j++) acc[i][j] += a[i] * bfr[j];
        }
        __syncthreads();
    }
#pragma unroll
    for (int i = 0; i < 8; i++) {
        int m = tr * 8 + i;
#pragma unroll
        for (int j4 = 0; j4 < CN / 4; j4++) {
            int col = col0 + tc * CN + j4 * 4;
            if (col < N) {
                float4 v = make_float4(acc[i][j4 * 4], acc[i][j4 * 4 + 1],
                                       acc[i][j4 * 4 + 2], acc[i][j4 * 4 + 3]);
                *reinterpret_cast<float4*>(&C[(long)m * ldc + col]) = v;
            }
        }
    }
}

// ---------------- split-K reduce: out[i] = sum_s part[s*stride + i] ------
__global__ void reduce_kernel(float* __restrict__ out,
                              const float* __restrict__ part,
                              int S, long total, long stride) {
    long i = (long)blockIdx.x * 256 + threadIdx.x;
    if (i >= total) return;
    float s = 0.f;
    for (int k = 0; k < S; k++) s += part[(long)k * stride + i];
    out[i] = s;
}

// ---------------- rmsnorm(q_a), rmsnorm(kv[:512]), rope(kv[512:576]) ------
__global__ void norm_rope_kernel(float* __restrict__ qa_io,
                                 const float* __restrict__ kv_in,
                                 float* __restrict__ kvlat,
                                 float* __restrict__ kpe,
                                 const float* __restrict__ q_ln_w,
                                 const float* __restrict__ kv_ln_w,
                                 const float* __restrict__ cosd,
                                 const float* __restrict__ sind) {
    const int b = blockIdx.x;
    const int t = threadIdx.x;
    __shared__ float sd[256];

    float* qa = qa_io + b * 1536;
    float ss = 0.f;
    for (int i = t; i < 1536; i += 256) { float v = qa[i]; ss += v * v; }
    sd[t] = ss; __syncthreads();
    for (int o = 128; o > 0; o >>= 1) { if (t < o) sd[t] += sd[t + o]; __syncthreads(); }
    float r = rsqrtf(sd[0] / 1536.f + EPSF);
    __syncthreads();
    for (int i = t; i < 1536; i += 256) qa[i] = qa[i] * r * q_ln_w[i];

    const float* kv = kv_in + b * 576;
    ss = 0.f;
    for (int i = t; i < 512; i += 256) { float v = kv[i]; ss += v * v; }
    sd[t] = ss; __syncthreads();
    for (int o = 128; o > 0; o >>= 1) { if (t < o) sd[t] += sd[t + o]; __syncthreads(); }
    float r2 = rsqrtf(sd[0] / 512.f + EPSF);
    __syncthreads();
    for (int i = t; i < 512; i += 256) kvlat[b * 512 + i] = kv[i] * r2 * kv_ln_w[i];

    if (t < 32) {
        float x1 = kv[512 + 2 * t], x2 = kv[512 + 2 * t + 1];
        float c = cosd[b * 32 + t], s = sind[b * 32 + t];
        kpe[b * 64 + 2 * t]     = x1 * c - x2 * s;
        kpe[b * 64 + 2 * t + 1] = x2 * c + x1 * s;
    }
}

// ---------------- rope q_pe into g_qeff[...,512:576] ----------------
__global__ void qpe_rope_kernel(const float* __restrict__ q,
                                const float* __restrict__ cosd,
                                const float* __restrict__ sind,
                                float* __restrict__ qeff) {
    int idx = blockIdx.x * 256 + threadIdx.x;  // 4096 = 32*128
    int b = idx >> 7, h = idx & 127;
    const float* src = q + b * 24576 + h * 192 + 128;
    float* dst = qeff + (long)(b * 128 + h) * 576 + 512;
#pragma unroll
    for (int i = 0; i < 32; i++) {
        float x1 = src[2 * i], x2 = src[2 * i + 1];
        float c = cosd[b * 32 + i], s = sind[b * 32 + i];
        dst[2 * i]     = x1 * c - x2 * s;
        dst[2 * i + 1] = x2 * c + x1 * s;
    }
}

// =====================================================================
// scores: per (b, mt, nt): Q[64h x 576] @ Keys[128tok x 576]^T
// 128 threads, 8x8 per thread, BK=8. Token tile == one cache block.
// =====================================================================
__global__ __launch_bounds__(128) void scores_kernel(
    const float* __restrict__ qeff,
    const float* __restrict__ kvlat,
    const float* __restrict__ kpe,
    const float* __restrict__ cache_kv,
    const float* __restrict__ cache_pe,
    const int* __restrict__ block_table,
    const int* __restrict__ slot_mapping,
    float* __restrict__ scores)
{
    const int nt = blockIdx.x, mt = blockIdx.y, b = blockIdx.z;
    __shared__ float As[8][68];    // [kk][m]
    __shared__ float Bs[8][132];   // [kk][n]
    const int t = threadIdx.x;
    const int tr = t >> 4, tc = t & 15;

    const int blkid = block_table[b * 16 + nt];
    const int slotm = slot_mapping[b];
    const int ovr = ((slotm >> 7) == blkid) ? (slotm & 127) : -1;

    const float* Ab = qeff + (long)b * 73728 + (long)(mt * 64) * 576;
    const float* kvb = cache_kv + (long)blkid * 65536;
    const float* peb = cache_pe + (long)blkid * 8192;

    float acc[8][8];
#pragma unroll
    for (int i = 0; i < 8; i++)
#pragma unroll
        for (int j = 0; j < 8; j++) acc[i][j] = 0.f;

    for (int k0 = 0; k0 < 576; k0 += 8) {
        // A: 64 rows x 8 k, transposed store
        {
            int m = t >> 1, kk0 = (t & 1) * 4;
            float4 v = *reinterpret_cast<const float4*>(&Ab[(long)m * 576 + k0 + kk0]);
            As[kk0 + 0][m] = v.x; As[kk0 + 1][m] = v.y;
            As[kk0 + 2][m] = v.z; As[kk0 + 3][m] = v.w;
        }
        // B: 128 tokens x 8 k, transposed store, with new-token override
#pragma unroll
        for (int i = 0; i < 2; i++) {
            int e = t + i * 128;
            int n = e >> 1, kk0 = (e & 1) * 4;
            float4 v;
            if (k0 < 512) {
                v = (n == ovr)
                    ? *reinterpret_cast<const float4*>(&kvlat[b * 512 + k0 + kk0])
                    : *reinterpret_cast<const float4*>(&kvb[(long)n * 512 + k0 + kk0]);
            } else {
                v = (n == ovr)
                    ? *reinterpret_cast<const float4*>(&kpe[b * 64 + (k0 - 512) + kk0])
                    : *reinterpret_cast<const float4*>(&peb[(long)n * 64 + (k0 - 512) + kk0]);
            }
            Bs[kk0 + 0][n] = v.x; Bs[kk0 + 1][n] = v.y;
            Bs[kk0 + 2][n] = v.z; Bs[kk0 + 3][n] = v.w;
        }
        __syncthreads();
#pragma unroll
        for (int kk = 0; kk < 8; kk++) {
            float a[8], bb[8];
            *reinterpret_cast<float4*>(&a[0]) = *reinterpret_cast<const float4*>(&As[kk][tr * 8]);
            *reinterpret_cast<float4*>(&a[4]) = *reinterpret_cast<const float4*>(&As[kk][tr * 8 + 4]);
            *reinterpret_cast<float4*>(&bb[0]) = *reinterpret_cast<const float4*>(&Bs[kk][tc * 8]);
            *reinterpret_cast<float4*>(&bb[4]) = *reinterpret_cast<const float4*>(&Bs[kk][tc * 8 + 4]);
#pragma unroll
            for (int i = 0; i < 8; i++)
#pragma unroll
                for (int j = 0; j < 8; j++) acc[i][j] += a[i] * bb[j];
        }
        __syncthreads();
    }
#pragma unroll
    for (int i = 0; i < 8; i++) {
        long row = (long)(b * 128 + mt * 64 + tr * 8 + i);
        int col = nt * 128 + tc * 8;
        float4 v0 = make_float4(acc[i][0] * SCALEF, acc[i][1] * SCALEF,
                                acc[i][2] * SCALEF, acc[i][3] * SCALEF);
        float4 v1 = make_float4(acc[i][4] * SCALEF, acc[i][5] * SCALEF,
                                acc[i][6] * SCALEF, acc[i][7] * SCALEF);
        *reinterpret_cast<float4*>(&scores[row * 2048 + col]) = v0;
        *reinterpret_cast<float4*>(&scores[row * 2048 + col + 4]) = v1;
    }
}

// ---------------- softmax per (b,h) row over 2048 with masking -------------
__global__ void softmax_kernel(float* __restrict__ scores,
                               const int* __restrict__ seq_lens) {
    const int row = blockIdx.x;
    const int b = row >> 7;
    const int L = seq_lens[b];
    float* p = scores + (long)row * 2048;
    const int t = threadIdx.x;
    __shared__ float sd[256];

    float m = -1e30f;
    for (int s = t; s < 2048; s += 256)
        if (s < L) m = fmaxf(m, p[s]);
    sd[t] = m; __syncthreads();
    for (int o = 128; o > 0; o >>= 1) { if (t < o) sd[t] = fmaxf(sd[t], sd[t + o]); __syncthreads(); }
    m = sd[0]; __syncthreads();

    float sum = 0.f;
    for (int s = t; s < 2048; s += 256) {
        float e = (s < L) ? __expf(p[s] - m) : 0.f;
        p[s] = e;
        sum += e;
    }
    sd[t] = sum; __syncthreads();
    for (int o = 128; o > 0; o >>= 1) { if (t < o) sd[t] += sd[t + o]; __syncthreads(); }
    float inv = 1.f / sd[0];
    for (int s = t; s < 2048; s += 256) p[s] *= inv;
}

// =====================================================================
// ctx: per (b, mt, nt): attn[64h x 2048] @ V[2048 x 128cols]
// 128 threads, 8x8 per thread, BK=8.
// =====================================================================
__global__ __launch_bounds__(128) void ctx_kernel(
    const float* __restrict__ scores,
    const float* __restrict__ kvlat,
    const float* __restrict__ cache_kv,
    const int* __restrict__ block_table,
    const int* __restrict__ slot_mapping,
    float* __restrict__ ctx)
{
    const int nt = blockIdx.x, mt = blockIdx.y, b = blockIdx.z;
    __shared__ float As[8][68];    // [kk][m]
    __shared__ float Bs[8][132];   // [kk][n]
    const int t = threadIdx.x;
    const int tr = t >> 4, tc = t & 15;
    const int slotm = slot_mapping[b];
    const int ovrBlk = slotm >> 7, ovrOff = slotm & 127;

    float acc[8][8];
#pragma unroll
    for (int i = 0; i < 8; i++)
#pragma unroll
        for (int j = 0; j < 8; j++) acc[i][j] = 0.f;

    for (int k0 = 0; k0 < 2048; k0 += 8) {
        // A: attn 64 rows x 8 k, transposed
        {
            int m = t >> 1, kk0 = (t & 1) * 4;
            long row = (long)(b * 128 + mt * 64 + m);
            float4 v = *reinterpret_cast<const float4*>(&scores[row * 2048 + k0 + kk0]);
            As[kk0 + 0][m] = v.x; As[kk0 + 1][m] = v.y;
            As[kk0 + 2][m] = v.z; As[kk0 + 3][m] = v.w;
        }
        // B: 8 token rows x 128 cols, direct
        const int blkid = block_table[b * 16 + (k0 >> 7)];
        const float* kvb = cache_kv + (long)blkid * 65536;
#pragma unroll
        for (int i = 0; i < 2; i++) {
            int e = t + i * 128;
            int kk = e >> 5, n0 = (e & 31) * 4;
            int soff = (k0 & 127) + kk;
            float4 v;
            if (blkid == ovrBlk && soff == ovrOff)
                v = *reinterpret_cast<const float4*>(&kvlat[b * 512 + nt * 128 + n0]);
            else
                v = *reinterpret_cast<const float4*>(&kvb[(long)soff * 512 + nt * 128 + n0]);
            *reinterpret_cast<float4*>(&Bs[kk][n0]) = v;
        }
        __syncthreads();
#pragma unroll
        for (int kk = 0; kk < 8; kk++) {
            float a[8], bb[8];
            *reinterpret_cast<float4*>(&a[0]) = *reinterpret_cast<const float4*>(&As[kk][tr * 8]);
            *reinterpret_cast<float4*>(&a[4]) = *reinterpret_cast<const float4*>(&As[kk][tr * 8 + 4]);
            *reinterpret_cast<float4*>(&bb[0]) = *reinterpret_cast<const float4*>(&Bs[kk][tc * 8]);
            *reinterpret_cast<float4*>(&bb[4]) = *reinterpret_cast<const float4*>(&Bs[kk][tc * 8 + 4]);
#pragma unroll
            for (int i = 0; i < 8; i++)
#pragma unroll
                for (int j = 0; j < 8; j++) acc[i][j] += a[i] * bb[j];
        }
        __syncthreads();
    }
#pragma unroll
    for (int i = 0; i < 8; i++) {
        long row = (long)(b * 128 + mt * 64 + tr * 8 + i);
        int col = nt * 128 + tc * 8;
        float4 v0 = make_float4(acc[i][0], acc[i][1], acc[i][2], acc[i][3]);
        float4 v1 = make_float4(acc[i][4], acc[i][5], acc[i][6], acc[i][7]);
        *reinterpret_cast<float4*>(&ctx[row * 512 + col]) = v0;
        *reinterpret_cast<float4*>(&ctx[row * 512 + col + 4]) = v1;
    }
}

// ------------------------------ host driver ------------------------------
extern "C" void kernel_launch(void* const* d_in, const int* in_sizes, int n_in,
                              void* d_out, int out_size) {
    const float* hidden    = (const float*)d_in[0];
    const float* cosd      = (const float*)d_in[1];
    const float* sind      = (const float*)d_in[2];
    const float* Wq_a      = (const float*)d_in[3];
    const float* q_ln_w    = (const float*)d_in[4];
    const float* Wq_b      = (const float*)d_in[5];
    const float* Wkv_a     = (const float*)d_in[6];
    const float* kv_ln_w   = (const float*)d_in[7];
    const float* Wukt      = (const float*)d_in[8];
    const float* Wuv       = (const float*)d_in[9];
    const float* Wo        = (const float*)d_in[10];
    const float* cache_kv  = (const float*)d_in[11];
    const float* cache_pe  = (const float*)d_in[12];
    const int*   block_tab = (const int*)d_in[13];
    const int*   slot_map  = (const int*)d_in[14];
    const int*   seq_lens  = (const int*)d_in[15];
    float* out = (float*)d_out;

    float *qa, *kvb, *kvlat, *kpe, *q, *qeff, *scores, *ctx, *headout, *part;
    cudaGetSymbolAddress((void**)&qa,      g_qa);
    cudaGetSymbolAddress((void**)&kvb,     g_kv);
    cudaGetSymbolAddress((void**)&kvlat,   g_kvlat);
    cudaGetSymbolAddress((void**)&kpe,     g_kpe);
    cudaGetSymbolAddress((void**)&q,       g_q);
    cudaGetSymbolAddress((void**)&qeff,    g_qeff);
    cudaGetSymbolAddress((void**)&scores,  g_scores);
    cudaGetSymbolAddress((void**)&ctx,     g_ctx);
    cudaGetSymbolAddress((void**)&headout, g_headout);
    cudaGetSymbolAddress((void**)&part,    g_part);

    // 1) q_a = hidden @ Wq_a  (K=5120, N=1536), split-K 80 x chunk 64
    smallgemm8<256><<<dim3(6, 80, 1), 128>>>(hidden, 5120, 0, Wq_a, 1536, 0,
                                             part, 1536, 0, 49152, 5120, 1536, 64);
    reduce_kernel<<<(49152 + 255) / 256, 256>>>(qa, part, 80, 49152, 49152);

    // 2) kv = hidden @ Wkv_a  (K=5120, N=576), split-K 80 x chunk 64
    //    (reuses 'part' AFTER step-1 reduce -> use second region of part)
    smallgemm8<256><<<dim3(3, 80, 1), 128>>>(hidden, 5120, 0, Wkv_a, 576, 0,
                                             part + 4194304, 576, 0, 18432, 5120, 576, 64);
    reduce_kernel<<<(18432 + 255) / 256, 256>>>(kvb, part + 4194304, 80, 18432, 18432);

    // 3) norms + k_pe rope
    norm_rope_kernel<<<32, 256>>>(qa, kvb, kvlat, kpe, q_ln_w, kv_ln_w, cosd, sind);

    // 4) q = q_a_norm @ Wq_b  (K=1536, N=24576), split-K 8 x chunk 192
    smallgemm8<256><<<dim3(96, 8, 1), 128>>>(qa, 1536, 0, Wq_b, 24576, 0,
                                             part, 24576, 0, 786432, 1536, 24576, 192);
    reduce_kernel<<<(786432 + 255) / 256, 256>>>(q, part, 8, 786432, 786432);

    // 5) rope q_pe -> qeff[..., 512:576]
    qpe_rope_kernel<<<16, 256>>>(q, cosd, sind, qeff);

    // 6) q_lat[b,h,:512] = q_nope[b,h] @ W_UK_T[h]  (per-head, K=128, N=512)
    smallgemm8<128><<<dim3(4, 1, 128), 128>>>(q, 24576, 192, Wukt, 512, 65536,
                                              qeff, 73728, 576, 0, 128, 512, 128);

    // 7) attention scores (1024 blocks)
    scores_kernel<<<dim3(16, 2, 32), 128>>>(qeff, kvlat, kpe, cache_kv, cache_pe,
                                            block_tab, slot_map, scores);

    // 8) softmax
    softmax_kernel<<<4096, 256>>>(scores, seq_lens);

    // 9) ctx = attn @ keys_kv (256 blocks)
    ctx_kernel<<<dim3(4, 2, 32), 128>>>(scores, kvlat, cache_kv, block_tab,
                                        slot_map, ctx);

    // 10) headout = ctx @ W_UV (per-head, K=512, N=128), split-K 4
    smallgemm8<128><<<dim3(1, 4, 128), 128>>>(ctx, 65536, 512, Wuv, 128, 65536,
                                              part, 16384, 128, 524288, 512, 128, 128);
    reduce_kernel<<<(524288 + 255) / 256, 256>>>(headout, part, 4, 524288, 524288);

    // 11) out = headout @ Wo  (K=16384, N=5120), split-K 32 x chunk 512
    smallgemm8<256><<<dim3(20, 32, 1), 128>>>(headout, 16384, 0, Wo, 5120, 0,
                                              part, 5120, 0, 163840, 16384, 5120, 512);
    reduce_kernel<<<(163840 + 255) / 256, 256>>>(out, part, 32, 163840, 163840);
}

// round 4
// speedup vs baseline: 9.6301x; 1.4721x over previous
#include <cuda_runtime.h>
#include <math.h>

#define EPSF 1e-6f
#define SCALEF 0.07216878364870323f  // 1/sqrt(192)

// ---------------- device scratch ----------------
__device__ float g_qa[32 * 1536];
__device__ float g_kv[32 * 576];
__device__ float g_kvlat[32 * 512];
__device__ float g_kpe[32 * 64];
__device__ float g_q[32 * 24576];
__device__ float g_qeff[32 * 128 * 576];   // [b][h][576] = [q_lat(512) | q_pe(64)]
__device__ float g_scores[32 * 128 * 2048];
__device__ float g_ctx[32 * 128 * 512];
__device__ float g_headout[32 * 16384];
__device__ float g_part[8 * 1024 * 1024];  // split-K partials

// ---------------- tf32 helpers ----------------
__device__ __forceinline__ unsigned f2tf(float f) {
    unsigned u;
    asm("cvt.rna.tf32.f32 %0, %1;" : "=r"(u) : "f"(f));
    return u;
}
__device__ __forceinline__ void mma_tf32(float c[4],
                                         unsigned a0, unsigned a1, unsigned a2, unsigned a3,
                                         unsigned b0, unsigned b1) {
    asm volatile("mma.sync.aligned.m16n8k8.row.col.f32.tf32.tf32.f32 "
                 "{%0,%1,%2,%3}, {%4,%5,%6,%7}, {%8,%9}, {%0,%1,%2,%3};"
                 : "+f"(c[0]), "+f"(c[1]), "+f"(c[2]), "+f"(c[3])
                 : "r"(a0), "r"(a1), "r"(a2), "r"(a3), "r"(b0), "r"(b1));
}

// =====================================================================
// tf32 MMA GEMM: C(32xN) = A(32xK) @ B(KxN), B row-major. Tile 32x128,
// 256 threads (8 warps: 2x4), split-K via grid.y, batch via grid.z.
// =====================================================================
__global__ __launch_bounds__(256) void mma_gemm32(
    const float* __restrict__ A, int lda, long sA,
    const float* __restrict__ B, int ldb, long sB,
    float* __restrict__ C, int ldc, long sC,
    long partStride, int K, int N, int kchunk)
{
    __shared__ unsigned As[32][20];    // [m][k], pitch 20
    __shared__ unsigned Bs[16][132];   // [k][n], pitch 132

    const int t = threadIdx.x, lane = t & 31, wid = t >> 5;
    const int warp_m = wid >> 2, warp_n = wid & 3;
    const int col0 = blockIdx.x * 128;
    const int k0b = blockIdx.y * kchunk;
    const int kend = min(K, k0b + kchunk);

    A += (long)blockIdx.z * sA;
    B += (long)blockIdx.z * sB;
    C += (long)blockIdx.z * sC + (long)blockIdx.y * partStride;

    float acc[4][4];
#pragma unroll
    for (int i = 0; i < 4; i++)
#pragma unroll
        for (int j = 0; j < 4; j++) acc[i][j] = 0.f;

    for (int k0 = k0b; k0 < kend; k0 += 16) {
        if (t < 128) {
            int m = t >> 2, kq = (t & 3) * 4;
            float4 v = *reinterpret_cast<const float4*>(&A[(long)m * lda + k0 + kq]);
            uint4 u = make_uint4(f2tf(v.x), f2tf(v.y), f2tf(v.z), f2tf(v.w));
            *reinterpret_cast<uint4*>(&As[m][kq]) = u;
        }
#pragma unroll
        for (int i = 0; i < 2; i++) {
            int e = t + i * 256;
            int kk = e >> 5, n0 = (e & 31) * 4;
            uint4 u = make_uint4(0u, 0u, 0u, 0u);
            if (col0 + n0 < N) {
                float4 v = *reinterpret_cast<const float4*>(&B[(long)(k0 + kk) * ldb + col0 + n0]);
                u = make_uint4(f2tf(v.x), f2tf(v.y), f2tf(v.z), f2tf(v.w));
            }
            *reinterpret_cast<uint4*>(&Bs[kk][n0]) = u;
        }
        __syncthreads();
#pragma unroll
        for (int kk = 0; kk < 16; kk += 8) {
            int ar = warp_m * 16 + (lane >> 2);
            int ak = kk + (lane & 3);
            unsigned a0 = As[ar][ak], a1 = As[ar + 8][ak];
            unsigned a2 = As[ar][ak + 4], a3 = As[ar + 8][ak + 4];
#pragma unroll
            for (int nt8 = 0; nt8 < 4; nt8++) {
                int bn = warp_n * 32 + nt8 * 8 + (lane >> 2);
                unsigned b0 = Bs[kk + (lane & 3)][bn];
                unsigned b1 = Bs[kk + 4 + (lane & 3)][bn];
                mma_tf32(acc[nt8], a0, a1, a2, a3, b0, b1);
            }
        }
        __syncthreads();
    }
    const int row = warp_m * 16 + (lane >> 2);
#pragma unroll
    for (int nt8 = 0; nt8 < 4; nt8++) {
        int col = col0 + warp_n * 32 + nt8 * 8 + 2 * (lane & 3);
        if (col < N) {
            *reinterpret_cast<float2*>(&C[(long)row * ldc + col]) =
                make_float2(acc[nt8][0], acc[nt8][1]);
            *reinterpret_cast<float2*>(&C[(long)(row + 8) * ldc + col]) =
                make_float2(acc[nt8][2], acc[nt8][3]);
        }
    }
}

// ---------------- split-K reduce ----------------
__global__ void reduce_kernel(float* __restrict__ out,
                              const float* __restrict__ part,
                              int S, long total, long stride) {
    long i = (long)blockIdx.x * 256 + threadIdx.x;
    if (i >= total) return;
    float s = 0.f;
    for (int k = 0; k < S; k++) s += part[(long)k * stride + i];
    out[i] = s;
}

// =====================================================================
// fp32 small GEMM (kept for per-head q_lat / W_UV)
// =====================================================================
template <int BN>
__global__ __launch_bounds__(128) void smallgemm8(
    const float* __restrict__ A, int lda, long sA,
    const float* __restrict__ B, int ldb, long sB,
    float* __restrict__ C, int ldc, long sC,
    long partStride, int K, int N, int kchunk)
{
    constexpr int CN = BN / 32;
    __shared__ float As[32][36];
    __shared__ float Bs[32][BN];

    const int t = threadIdx.x;
    const int tr = t >> 5;
    const int tc = t & 31;
    const int col0 = blockIdx.x * BN;
    const int k0b = blockIdx.y * kchunk;
    const int kend = min(K, k0b + kchunk);

    A += (long)blockIdx.z * sA;
    B += (long)blockIdx.z * sB;
    C += (long)blockIdx.z * sC + (long)blockIdx.y * partStride;

    float acc[8][CN];
#pragma unroll
    for (int i = 0; i < 8; i++)
#pragma unroll
        for (int j = 0; j < CN; j++) acc[i][j] = 0.f;

    for (int k0 = k0b; k0 < kend; k0 += 32) {
#pragma unroll
        for (int i = 0; i < 2; i++) {
            int e = t + i * 128;
            int m = e >> 3, kk0 = (e & 7) * 4;
            float4 v = *reinterpret_cast<const float4*>(&A[(long)m * lda + k0 + kk0]);
            *reinterpret_cast<float4*>(&As[m][kk0]) = v;
        }
#pragma unroll
        for (int i = 0; i < BN / 16; i++) {
            int e = t + i * 128;
            int kk = e / (BN / 4);
            int n0 = (e % (BN / 4)) * 4;
            float4 v = make_float4(0.f, 0.f, 0.f, 0.f);
            if (col0 + n0 < N)
                v = *reinterpret_cast<const float4*>(&B[(long)(k0 + kk) * ldb + col0 + n0]);
            *reinterpret_cast<float4*>(&Bs[kk][n0]) = v;
        }
        __syncthreads();
#pragma unroll
        for (int kk = 0; kk < 32; kk++) {
            float a[8];
#pragma unroll
            for (int i = 0; i < 8; i++) a[i] = As[tr * 8 + i][kk];
            float bfr[CN];
#pragma unroll
            for (int j4 = 0; j4 < CN / 4; j4++)
                *reinterpret_cast<float4*>(&bfr[j4 * 4]) =
                    *reinterpret_cast<const float4*>(&Bs[kk][tc * CN + j4 * 4]);
#pragma unroll
            for (int i = 0; i < 8; i++)
#pragma unroll
                for (int j = 0; j < CN; j++) acc[i][j] += a[i] * bfr[j];
        }
        __syncthreads();
    }
#pragma unroll
    for (int i = 0; i < 8; i++) {
        int m = tr * 8 + i;
#pragma unroll
        for (int j4 = 0; j4 < CN / 4; j4++) {
            int col = col0 + tc * CN + j4 * 4;
            if (col < N) {
                float4 v = make_float4(acc[i][j4 * 4], acc[i][j4 * 4 + 1],
                                       acc[i][j4 * 4 + 2], acc[i][j4 * 4 + 3]);
                *reinterpret_cast<float4*>(&C[(long)m * ldc + col]) = v;
            }
        }
    }
}

// ---------------- norms + k_pe rope ----------------
__global__ void norm_rope_kernel(float* __restrict__ qa_io,
                                 const float* __restrict__ kv_in,
                                 float* __restrict__ kvlat,
                                 float* __restrict__ kpe,
                                 const float* __restrict__ q_ln_w,
                                 const float* __restrict__ kv_ln_w,
                                 const float* __restrict__ cosd,
                                 const float* __restrict__ sind) {
    const int b = blockIdx.x;
    const int t = threadIdx.x;
    __shared__ float sd[256];

    float* qa = qa_io + b * 1536;
    float ss = 0.f;
    for (int i = t; i < 1536; i += 256) { float v = qa[i]; ss += v * v; }
    sd[t] = ss; __syncthreads();
    for (int o = 128; o > 0; o >>= 1) { if (t < o) sd[t] += sd[t + o]; __syncthreads(); }
    float r = rsqrtf(sd[0] / 1536.f + EPSF);
    __syncthreads();
    for (int i = t; i < 1536; i += 256) qa[i] = qa[i] * r * q_ln_w[i];

    const float* kv = kv_in + b * 576;
    ss = 0.f;
    for (int i = t; i < 512; i += 256) { float v = kv[i]; ss += v * v; }
    sd[t] = ss; __syncthreads();
    for (int o = 128; o > 0; o >>= 1) { if (t < o) sd[t] += sd[t + o]; __syncthreads(); }
    float r2 = rsqrtf(sd[0] / 512.f + EPSF);
    __syncthreads();
    for (int i = t; i < 512; i += 256) kvlat[b * 512 + i] = kv[i] * r2 * kv_ln_w[i];

    if (t < 32) {
        float x1 = kv[512 + 2 * t], x2 = kv[512 + 2 * t + 1];
        float c = cosd[b * 32 + t], s = sind[b * 32 + t];
        kpe[b * 64 + 2 * t]     = x1 * c - x2 * s;
        kpe[b * 64 + 2 * t + 1] = x2 * c + x1 * s;
    }
}

// ---------------- rope q_pe into g_qeff[...,512:576] ----------------
__global__ void qpe_rope_kernel(const float* __restrict__ q,
                                const float* __restrict__ cosd,
                                const float* __restrict__ sind,
                                float* __restrict__ qeff) {
    int idx = blockIdx.x * 256 + threadIdx.x;
    int b = idx >> 7, h = idx & 127;
    const float* src = q + b * 24576 + h * 192 + 128;
    float* dst = qeff + (long)(b * 128 + h) * 576 + 512;
#pragma unroll
    for (int i = 0; i < 32; i++) {
        float x1 = src[2 * i], x2 = src[2 * i + 1];
        float c = cosd[b * 32 + i], s = sind[b * 32 + i];
        dst[2 * i]     = x1 * c - x2 * s;
        dst[2 * i + 1] = x2 * c + x1 * s;
    }
}

// =====================================================================
// scores (tf32 MMA): per (nt,mt,b): Q[64h x 576] @ Keys[128tok x 576]^T
// 256 threads = 8 warps (4x2); warp tile 16x64.
// =====================================================================
__global__ __launch_bounds__(256) void mma_scores(
    const float* __restrict__ qeff,
    const float* __restrict__ kvlat,
    const float* __restrict__ kpe,
    const float* __restrict__ cache_kv,
    const float* __restrict__ cache_pe,
    const int* __restrict__ block_table,
    const int* __restrict__ slot_mapping,
    float* __restrict__ scores)
{
    const int nt = blockIdx.x, mt = blockIdx.y, b = blockIdx.z;
    __shared__ unsigned As[64][20];    // [m][k]
    __shared__ unsigned Bs[16][132];   // [k][n]
    const int t = threadIdx.x, lane = t & 31, wid = t >> 5;
    const int warp_m = wid >> 1, warp_n = wid & 1;

    const int blkid = block_table[b * 16 + nt];
    const int slotm = slot_mapping[b];
    const int ovr = ((slotm >> 7) == blkid) ? (slotm & 127) : -1;

    const float* Ab = qeff + (long)b * 73728 + (long)(mt * 64) * 576;
    const float* kvb = cache_kv + (long)blkid * 65536;
    const float* peb = cache_pe + (long)blkid * 8192;

    float acc[8][4];
#pragma unroll
    for (int i = 0; i < 8; i++)
#pragma unroll
        for (int j = 0; j < 4; j++) acc[i][j] = 0.f;

    for (int k0 = 0; k0 < 576; k0 += 16) {
        // A: 64 x 16
        {
            int m = t >> 2, kq = (t & 3) * 4;
            float4 v = *reinterpret_cast<const float4*>(&Ab[(long)m * 576 + k0 + kq]);
            uint4 u = make_uint4(f2tf(v.x), f2tf(v.y), f2tf(v.z), f2tf(v.w));
            *reinterpret_cast<uint4*>(&As[m][kq]) = u;
        }
        // B: 128 tokens x 16 k, transposed into [k][n]
#pragma unroll
        for (int i = 0; i < 2; i++) {
            int e = t + i * 256;
            int n = e >> 2, kq = (e & 3) * 4;
            float4 v;
            if (k0 < 512) {
                v = (n == ovr)
                    ? *reinterpret_cast<const float4*>(&kvlat[b * 512 + k0 + kq])
                    : *reinterpret_cast<const float4*>(&kvb[(long)n * 512 + k0 + kq]);
            } else {
                v = (n == ovr)
                    ? *reinterpret_cast<const float4*>(&kpe[b * 64 + (k0 - 512) + kq])
                    : *reinterpret_cast<const float4*>(&peb[(long)n * 64 + (k0 - 512) + kq]);
            }
            Bs[kq + 0][n] = f2tf(v.x); Bs[kq + 1][n] = f2tf(v.y);
            Bs[kq + 2][n] = f2tf(v.z); Bs[kq + 3][n] = f2tf(v.w);
        }
        __syncthreads();
#pragma unroll
        for (int kk = 0; kk < 16; kk += 8) {
            int ar = warp_m * 16 + (lane >> 2);
            int ak = kk + (lane & 3);
            unsigned a0 = As[ar][ak], a1 = As[ar + 8][ak];
            unsigned a2 = As[ar][ak + 4], a3 = As[ar + 8][ak + 4];
#pragma unroll
            for (int nt8 = 0; nt8 < 8; nt8++) {
                int bn = warp_n * 64 + nt8 * 8 + (lane >> 2);
                unsigned b0 = Bs[kk + (lane & 3)][bn];
                unsigned b1 = Bs[kk + 4 + (lane & 3)][bn];
                mma_tf32(acc[nt8], a0, a1, a2, a3, b0, b1);
            }
        }
        __syncthreads();
    }
    const long row0 = (long)(b * 128 + mt * 64 + warp_m * 16 + (lane >> 2));
#pragma unroll
    for (int nt8 = 0; nt8 < 8; nt8++) {
        int col = nt * 128 + warp_n * 64 + nt8 * 8 + 2 * (lane & 3);
        *reinterpret_cast<float2*>(&scores[row0 * 2048 + col]) =
            make_float2(acc[nt8][0] * SCALEF, acc[nt8][1] * SCALEF);
        *reinterpret_cast<float2*>(&scores[(row0 + 8) * 2048 + col]) =
            make_float2(acc[nt8][2] * SCALEF, acc[nt8][3] * SCALEF);
    }
}

// ---------------- softmax ----------------
__global__ void softmax_kernel(float* __restrict__ scores,
                               const int* __restrict__ seq_lens) {
    const int row = blockIdx.x;
    const int b = row >> 7;
    const int L = seq_lens[b];
    float* p = scores + (long)row * 2048;
    const int t = threadIdx.x;
    __shared__ float sd[256];

    float m = -1e30f;
    for (int s = t; s < 2048; s += 256)
        if (s < L) m = fmaxf(m, p[s]);
    sd[t] = m; __syncthreads();
    for (int o = 128; o > 0; o >>= 1) { if (t < o) sd[t] = fmaxf(sd[t], sd[t + o]); __syncthreads(); }
    m = sd[0]; __syncthreads();

    float sum = 0.f;
    for (int s = t; s < 2048; s += 256) {
        float e = (s < L) ? __expf(p[s] - m) : 0.f;
        p[s] = e;
        sum += e;
    }
    sd[t] = sum; __syncthreads();
    for (int o = 128; o > 0; o >>= 1) { if (t < o) sd[t] += sd[t + o]; __syncthreads(); }
    float inv = 1.f / sd[0];
    for (int s = t; s < 2048; s += 256) p[s] *= inv;
}

// =====================================================================
// ctx (tf32 MMA): per (nt,mt,b): attn[64h x 2048] @ V[2048 x 128cols]
// =====================================================================
__global__ __launch_bounds__(256) void mma_ctx(
    const float* __restrict__ scores,
    const float* __restrict__ kvlat,
    const float* __restrict__ cache_kv,
    const int* __restrict__ block_table,
    const int* __restrict__ slot_mapping,
    float* __restrict__ ctx)
{
    const int nt = blockIdx.x, mt = blockIdx.y, b = blockIdx.z;
    __shared__ unsigned As[64][20];
    __shared__ unsigned Bs[16][132];
    const int t = threadIdx.x, lane = t & 31, wid = t >> 5;
    const int warp_m = wid >> 1, warp_n = wid & 1;
    const int slotm = slot_mapping[b];
    const int ovrBlk = slotm >> 7, ovrOff = slotm & 127;

    float acc[8][4];
#pragma unroll
    for (int i = 0; i < 8; i++)
#pragma unroll
        for (int j = 0; j < 4; j++) acc[i][j] = 0.f;

    for (int k0 = 0; k0 < 2048; k0 += 16) {
        // A: attn 64 rows x 16 k
        {
            int m = t >> 2, kq = (t & 3) * 4;
            long row = (long)(b * 128 + mt * 64 + m);
            float4 v = *reinterpret_cast<const float4*>(&scores[row * 2048 + k0 + kq]);
            uint4 u = make_uint4(f2tf(v.x), f2tf(v.y), f2tf(v.z), f2tf(v.w));
            *reinterpret_cast<uint4*>(&As[m][kq]) = u;
        }
        // B: 16 token rows x 128 cols
        const int blkid = block_table[b * 16 + (k0 >> 7)];
        const float* kvb = cache_kv + (long)blkid * 65536;
#pragma unroll
        for (int i = 0; i < 2; i++) {
            int e = t + i * 256;
            int kk = e >> 5, n0 = (e & 31) * 4;
            int soff = (k0 & 127) + kk;
            float4 v;
            if (blkid == ovrBlk && soff == ovrOff)
                v = *reinterpret_cast<const float4*>(&kvlat[b * 512 + nt * 128 + n0]);
            else
                v = *reinterpret_cast<const float4*>(&kvb[(long)soff * 512 + nt * 128 + n0]);
            uint4 u = make_uint4(f2tf(v.x), f2tf(v.y), f2tf(v.z), f2tf(v.w));
            *reinterpret_cast<uint4*>(&Bs[kk][n0]) = u;
        }
        __syncthreads();
#pragma unroll
        for (int kk = 0; kk < 16; kk += 8) {
            int ar = warp_m * 16 + (lane >> 2);
            int ak = kk + (lane & 3);
            unsigned a0 = As[ar][ak], a1 = As[ar + 8][ak];
            unsigned a2 = As[ar][ak + 4], a3 = As[ar + 8][ak + 4];
#pragma unroll
            for (int nt8 = 0; nt8 < 8; nt8++) {
                int bn = warp_n * 64 + nt8 * 8 + (lane >> 2);
                unsigned b0 = Bs[kk + (lane & 3)][bn];
                unsigned b1 = Bs[kk + 4 + (lane & 3)][bn];
                mma_tf32(acc[nt8], a0, a1, a2, a3, b0, b1);
            }
        }
        __syncthreads();
    }
    const long row0 = (long)(b * 128 + mt * 64 + warp_m * 16 + (lane >> 2));
#pragma unroll
    for (int nt8 = 0; nt8 < 8; nt8++) {
        int col = nt * 128 + warp_n * 64 + nt8 * 8 + 2 * (lane & 3);
        *reinterpret_cast<float2*>(&ctx[row0 * 512 + col]) =
            make_float2(acc[nt8][0], acc[nt8][1]);
        *reinterpret_cast<float2*>(&ctx[(row0 + 8) * 512 + col]) =
            make_float2(acc[nt8][2], acc[nt8][3]);
    }
}

// ------------------------------ host driver ------------------------------
extern "C" void kernel_launch(void* const* d_in, const int* in_sizes, int n_in,
                              void* d_out, int out_size) {
    const float* hidden    = (const float*)d_in[0];
    const float* cosd      = (const float*)d_in[1];
    const float* sind      = (const float*)d_in[2];
    const float* Wq_a      = (const float*)d_in[3];
    const float* q_ln_w    = (const float*)d_in[4];
    const float* Wq_b      = (const float*)d_in[5];
    const float* Wkv_a     = (const float*)d_in[6];
    const float* kv_ln_w   = (const float*)d_in[7];
    const float* Wukt      = (const float*)d_in[8];
    const float* Wuv       = (const float*)d_in[9];
    const float* Wo        = (const float*)d_in[10];
    const float* cache_kv  = (const float*)d_in[11];
    const float* cache_pe  = (const float*)d_in[12];
    const int*   block_tab = (const int*)d_in[13];
    const int*   slot_map  = (const int*)d_in[14];
    const int*   seq_lens  = (const int*)d_in[15];
    float* out = (float*)d_out;

    float *qa, *kvb, *kvlat, *kpe, *q, *qeff, *scores, *ctx, *headout, *part;
    cudaGetSymbolAddress((void**)&qa,      g_qa);
    cudaGetSymbolAddress((void**)&kvb,     g_kv);
    cudaGetSymbolAddress((void**)&kvlat,   g_kvlat);
    cudaGetSymbolAddress((void**)&kpe,     g_kpe);
    cudaGetSymbolAddress((void**)&q,       g_q);
    cudaGetSymbolAddress((void**)&qeff,    g_qeff);
    cudaGetSymbolAddress((void**)&scores,  g_scores);
    cudaGetSymbolAddress((void**)&ctx,     g_ctx);
    cudaGetSymbolAddress((void**)&headout, g_headout);
    cudaGetSymbolAddress((void**)&part,    g_part);

    // 1) q_a = hidden @ Wq_a  (K=5120, N=1536), splitK 16 x 320
    mma_gemm32<<<dim3(12, 16, 1), 256>>>(hidden, 5120, 0, Wq_a, 1536, 0,
                                         part, 1536, 0, 49152, 5120, 1536, 320);
    reduce_kernel<<<(49152 + 255) / 256, 256>>>(qa, part, 16, 49152, 49152);

    // 2) kv = hidden @ Wkv_a  (K=5120, N=576), splitK 16 x 320
    mma_gemm32<<<dim3(5, 16, 1), 256>>>(hidden, 5120, 0, Wkv_a, 576, 0,
                                        part, 576, 0, 18432, 5120, 576, 320);
    reduce_kernel<<<(18432 + 255) / 256, 256>>>(kvb, part, 16, 18432, 18432);

    // 3) norms + k_pe rope
    norm_rope_kernel<<<32, 256>>>(qa, kvb, kvlat, kpe, q_ln_w, kv_ln_w, cosd, sind);

    // 4) q = q_a_norm @ Wq_b  (K=1536, N=24576), splitK 2 x 768
    mma_gemm32<<<dim3(192, 2, 1), 256>>>(qa, 1536, 0, Wq_b, 24576, 0,
                                         part, 24576, 0, 786432, 1536, 24576, 768);
    reduce_kernel<<<(786432 + 255) / 256, 256>>>(q, part, 2, 786432, 786432);

    // 5) rope q_pe -> qeff[..., 512:576]
    qpe_rope_kernel<<<16, 256>>>(q, cosd, sind, qeff);

    // 6) q_lat[b,h,:512] = q_nope[b,h] @ W_UK_T[h]  (per-head, fp32)
    smallgemm8<128><<<dim3(4, 1, 128), 128>>>(q, 24576, 192, Wukt, 512, 65536,
                                              qeff, 73728, 576, 0, 128, 512, 128);

    // 7) attention scores (tf32 MMA, 1024 blocks)
    mma_scores<<<dim3(16, 2, 32), 256>>>(qeff, kvlat, kpe, cache_kv, cache_pe,
                                         block_tab, slot_map, scores);

    // 8) softmax
    softmax_kernel<<<4096, 256>>>(scores, seq_lens);

    // 9) ctx = attn @ keys_kv (tf32 MMA, 256 blocks)
    mma_ctx<<<dim3(4, 2, 32), 256>>>(scores, kvlat, cache_kv, block_tab,
                                     slot_map, ctx);

    // 10) headout = ctx @ W_UV (per-head, fp32), splitK 4
    smallgemm8<128><<<dim3(1, 4, 128), 128>>>(ctx, 65536, 512, Wuv, 128, 65536,
                                              part, 16384, 128, 524288, 512, 128, 128);
    reduce_kernel<<<(524288 + 255) / 256, 256>>>(headout, part, 4, 524288, 524288);

    // 11) out = headout @ Wo  (K=16384, N=5120), splitK 8 x 2048
    mma_gemm32<<<dim3(40, 8, 1), 256>>>(headout, 16384, 0, Wo, 5120, 0,
                                        part, 5120, 0, 163840, 16384, 5120, 2048);
    reduce_kernel<<<(163840 + 255) / 256, 256>>>(out, part, 8, 163840, 163840);
}

// round 5
// speedup vs baseline: 11.4532x; 1.1893x over previous
#include <cuda_runtime.h>
#include <math.h>

#define EPSF 1e-6f
#define SCALEF 0.07216878364870323f  // 1/sqrt(192)

// ---------------- device scratch ----------------
__device__ float g_qa[32 * 1536];
__device__ float g_kv[32 * 576];
__device__ float g_kvlat[32 * 512];
__device__ float g_kpe[32 * 64];
__device__ float g_q[32 * 24576];
__device__ float g_qeff[32 * 128 * 576];   // [b][h][576] = [q_lat(512) | q_pe(64)]
__device__ float g_scores[32 * 128 * 2048];
__device__ float g_ctx[32 * 128 * 512];
__device__ float g_headout[32 * 16384];
__device__ float g_part[8 * 1024 * 1024];  // split-K partials

// ---------------- tf32 helpers ----------------
__device__ __forceinline__ unsigned f2tf(float f) {
    unsigned u;
    asm("cvt.rna.tf32.f32 %0, %1;" : "=r"(u) : "f"(f));
    return u;
}
__device__ __forceinline__ void mma_tf32(float c[4],
                                         unsigned a0, unsigned a1, unsigned a2, unsigned a3,
                                         unsigned b0, unsigned b1) {
    asm volatile("mma.sync.aligned.m16n8k8.row.col.f32.tf32.tf32.f32 "
                 "{%0,%1,%2,%3}, {%4,%5,%6,%7}, {%8,%9}, {%0,%1,%2,%3};"
                 : "+f"(c[0]), "+f"(c[1]), "+f"(c[2]), "+f"(c[3])
                 : "r"(a0), "r"(a1), "r"(a2), "r"(a3), "r"(b0), "r"(b1));
}

// =====================================================================
// tf32 MMA GEMM (double-buffered): C(32xN) = A(32xK) @ B(KxN).
// Tile 32x128, 256 threads (8 warps: 2x4), split-K grid.y, batch grid.z.
// =====================================================================
__global__ __launch_bounds__(256) void mma_gemm32(
    const float* __restrict__ A, int lda, long sA,
    const float* __restrict__ B, int ldb, long sB,
    float* __restrict__ C, int ldc, long sC,
    long partStride, int K, int N, int kchunk)
{
    __shared__ unsigned As[2][32][20];
    __shared__ unsigned Bs[2][16][132];

    const int t = threadIdx.x, lane = t & 31, wid = t >> 5;
    const int warp_m = wid >> 2, warp_n = wid & 3;
    const int lq = lane >> 2, lr = lane & 3;
    const int col0 = blockIdx.x * 128;
    const int k0b = blockIdx.y * kchunk;
    const int kend = min(K, k0b + kchunk);
    const int nIter = (kend - k0b) >> 4;

    A += (long)blockIdx.z * sA;
    B += (long)blockIdx.z * sB;
    C += (long)blockIdx.z * sC + (long)blockIdx.y * partStride;

    const int am = t >> 2, akq = (t & 3) * 4;       // A staging coords (t<128)
    const int bk0 = t >> 5, bn0 = (t & 31) * 4;     // B staging elem 0
    const int bk1 = (t + 256) >> 5, bn1 = bn0;      // B staging elem 1
    const bool bok = (col0 + bn0 < N);

    float4 fa, fb0, fb1;
    // prologue: fetch tile 0
    if (t < 128) fa = *reinterpret_cast<const float4*>(&A[(long)am * lda + k0b + akq]);
    if (bok) {
        fb0 = *reinterpret_cast<const float4*>(&B[(long)(k0b + bk0) * ldb + col0 + bn0]);
        fb1 = *reinterpret_cast<const float4*>(&B[(long)(k0b + bk1) * ldb + col0 + bn1]);
    } else { fb0 = fb1 = make_float4(0.f, 0.f, 0.f, 0.f); }
    if (t < 128)
        *reinterpret_cast<uint4*>(&As[0][am][akq]) =
            make_uint4(f2tf(fa.x), f2tf(fa.y), f2tf(fa.z), f2tf(fa.w));
    *reinterpret_cast<uint4*>(&Bs[0][bk0][bn0]) =
        make_uint4(f2tf(fb0.x), f2tf(fb0.y), f2tf(fb0.z), f2tf(fb0.w));
    *reinterpret_cast<uint4*>(&Bs[0][bk1][bn1]) =
        make_uint4(f2tf(fb1.x), f2tf(fb1.y), f2tf(fb1.z), f2tf(fb1.w));
    __syncthreads();

    float acc[4][4];
#pragma unroll
    for (int i = 0; i < 4; i++)
#pragma unroll
        for (int j = 0; j < 4; j++) acc[i][j] = 0.f;

    for (int it = 0; it < nIter; it++) {
        const int cur = it & 1, nxt = cur ^ 1;
        const bool hasNext = (it + 1 < nIter);
        if (hasNext) {
            int kn = k0b + (it + 1) * 16;
            if (t < 128) fa = *reinterpret_cast<const float4*>(&A[(long)am * lda + kn + akq]);
            if (bok) {
                fb0 = *reinterpret_cast<const float4*>(&B[(long)(kn + bk0) * ldb + col0 + bn0]);
                fb1 = *reinterpret_cast<const float4*>(&B[(long)(kn + bk1) * ldb + col0 + bn1]);
            }
        }
#pragma unroll
        for (int kk = 0; kk < 16; kk += 8) {
            int ar = warp_m * 16 + lq;
            int ak = kk + lr;
            unsigned a0 = As[cur][ar][ak], a1 = As[cur][ar + 8][ak];
            unsigned a2 = As[cur][ar][ak + 4], a3 = As[cur][ar + 8][ak + 4];
#pragma unroll
            for (int nt8 = 0; nt8 < 4; nt8++) {
                int bn = warp_n * 32 + nt8 * 8 + lq;
                unsigned b0 = Bs[cur][kk + lr][bn];
                unsigned b1 = Bs[cur][kk + 4 + lr][bn];
                mma_tf32(acc[nt8], a0, a1, a2, a3, b0, b1);
            }
        }
        if (hasNext) {
            if (t < 128)
                *reinterpret_cast<uint4*>(&As[nxt][am][akq]) =
                    make_uint4(f2tf(fa.x), f2tf(fa.y), f2tf(fa.z), f2tf(fa.w));
            *reinterpret_cast<uint4*>(&Bs[nxt][bk0][bn0]) =
                make_uint4(f2tf(fb0.x), f2tf(fb0.y), f2tf(fb0.z), f2tf(fb0.w));
            *reinterpret_cast<uint4*>(&Bs[nxt][bk1][bn1]) =
                make_uint4(f2tf(fb1.x), f2tf(fb1.y), f2tf(fb1.z), f2tf(fb1.w));
        }
        __syncthreads();
    }
    const int row = warp_m * 16 + lq;
#pragma unroll
    for (int nt8 = 0; nt8 < 4; nt8++) {
        int col = col0 + warp_n * 32 + nt8 * 8 + 2 * lr;
        if (col < N) {
            *reinterpret_cast<float2*>(&C[(long)row * ldc + col]) =
                make_float2(acc[nt8][0], acc[nt8][1]);
            *reinterpret_cast<float2*>(&C[(long)(row + 8) * ldc + col]) =
                make_float2(acc[nt8][2], acc[nt8][3]);
        }
    }
}

// ---------------- split-K reduce ----------------
__global__ void reduce_kernel(float* __restrict__ out,
                              const float* __restrict__ part,
                              int S, long total, long stride) {
    long i = (long)blockIdx.x * 256 + threadIdx.x;
    if (i >= total) return;
    float s = 0.f;
    for (int k = 0; k < S; k++) s += part[(long)k * stride + i];
    out[i] = s;
}

// =====================================================================
// fp32 small GEMM (per-head q_lat / W_UV)
// =====================================================================
template <int BN>
__global__ __launch_bounds__(128) void smallgemm8(
    const float* __restrict__ A, int lda, long sA,
    const float* __restrict__ B, int ldb, long sB,
    float* __restrict__ C, int ldc, long sC,
    long partStride, int K, int N, int kchunk)
{
    constexpr int CN = BN / 32;
    __shared__ float As[32][36];
    __shared__ float Bs[32][BN];

    const int t = threadIdx.x;
    const int tr = t >> 5;
    const int tc = t & 31;
    const int col0 = blockIdx.x * BN;
    const int k0b = blockIdx.y * kchunk;
    const int kend = min(K, k0b + kchunk);

    A += (long)blockIdx.z * sA;
    B += (long)blockIdx.z * sB;
    C += (long)blockIdx.z * sC + (long)blockIdx.y * partStride;

    float acc[8][CN];
#pragma unroll
    for (int i = 0; i < 8; i++)
#pragma unroll
        for (int j = 0; j < CN; j++) acc[i][j] = 0.f;

    for (int k0 = k0b; k0 < kend; k0 += 32) {
#pragma unroll
        for (int i = 0; i < 2; i++) {
            int e = t + i * 128;
            int m = e >> 3, kk0 = (e & 7) * 4;
            float4 v = *reinterpret_cast<const float4*>(&A[(long)m * lda + k0 + kk0]);
            *reinterpret_cast<float4*>(&As[m][kk0]) = v;
        }
#pragma unroll
        for (int i = 0; i < BN / 16; i++) {
            int e = t + i * 128;
            int kk = e / (BN / 4);
            int n0 = (e % (BN / 4)) * 4;
            float4 v = make_float4(0.f, 0.f, 0.f, 0.f);
            if (col0 + n0 < N)
                v = *reinterpret_cast<const float4*>(&B[(long)(k0 + kk) * ldb + col0 + n0]);
            *reinterpret_cast<float4*>(&Bs[kk][n0]) = v;
        }
        __syncthreads();
#pragma unroll
        for (int kk = 0; kk < 32; kk++) {
            float a[8];
#pragma unroll
            for (int i = 0; i < 8; i++) a[i] = As[tr * 8 + i][kk];
            float bfr[CN];
#pragma unroll
            for (int j4 = 0; j4 < CN / 4; j4++)
                *reinterpret_cast<float4*>(&bfr[j4 * 4]) =
                    *reinterpret_cast<const float4*>(&Bs[kk][tc * CN + j4 * 4]);
#pragma unroll
            for (int i = 0; i < 8; i++)
#pragma unroll
                for (int j = 0; j < CN; j++) acc[i][j] += a[i] * bfr[j];
        }
        __syncthreads();
    }
#pragma unroll
    for (int i = 0; i < 8; i++) {
        int m = tr * 8 + i;
#pragma unroll
        for (int j4 = 0; j4 < CN / 4; j4++) {
            int col = col0 + tc * CN + j4 * 4;
            if (col < N) {
                float4 v = make_float4(acc[i][j4 * 4], acc[i][j4 * 4 + 1],
                                       acc[i][j4 * 4 + 2], acc[i][j4 * 4 + 3]);
                *reinterpret_cast<float4*>(&C[(long)m * ldc + col]) = v;
            }
        }
    }
}

// ---------------- norms + k_pe rope ----------------
__global__ void norm_rope_kernel(float* __restrict__ qa_io,
                                 const float* __restrict__ kv_in,
                                 float* __restrict__ kvlat,
                                 float* __restrict__ kpe,
                                 const float* __restrict__ q_ln_w,
                                 const float* __restrict__ kv_ln_w,
                                 const float* __restrict__ cosd,
                                 const float* __restrict__ sind) {
    const int b = blockIdx.x;
    const int t = threadIdx.x;
    __shared__ float sd[256];

    float* qa = qa_io + b * 1536;
    float ss = 0.f;
    for (int i = t; i < 1536; i += 256) { float v = qa[i]; ss += v * v; }
    sd[t] = ss; __syncthreads();
    for (int o = 128; o > 0; o >>= 1) { if (t < o) sd[t] += sd[t + o]; __syncthreads(); }
    float r = rsqrtf(sd[0] / 1536.f + EPSF);
    __syncthreads();
    for (int i = t; i < 1536; i += 256) qa[i] = qa[i] * r * q_ln_w[i];

    const float* kv = kv_in + b * 576;
    ss = 0.f;
    for (int i = t; i < 512; i += 256) { float v = kv[i]; ss += v * v; }
    sd[t] = ss; __syncthreads();
    for (int o = 128; o > 0; o >>= 1) { if (t < o) sd[t] += sd[t + o]; __syncthreads(); }
    float r2 = rsqrtf(sd[0] / 512.f + EPSF);
    __syncthreads();
    for (int i = t; i < 512; i += 256) kvlat[b * 512 + i] = kv[i] * r2 * kv_ln_w[i];

    if (t < 32) {
        float x1 = kv[512 + 2 * t], x2 = kv[512 + 2 * t + 1];
        float c = cosd[b * 32 + t], s = sind[b * 32 + t];
        kpe[b * 64 + 2 * t]     = x1 * c - x2 * s;
        kpe[b * 64 + 2 * t + 1] = x2 * c + x1 * s;
    }
}

// ---------------- rope q_pe into g_qeff[...,512:576] ----------------
__global__ void qpe_rope_kernel(const float* __restrict__ q,
                                const float* __restrict__ cosd,
                                const float* __restrict__ sind,
                                float* __restrict__ qeff) {
    int idx = blockIdx.x * 256 + threadIdx.x;
    int b = idx >> 7, h = idx & 127;
    const float* src = q + b * 24576 + h * 192 + 128;
    float* dst = qeff + (long)(b * 128 + h) * 576 + 512;
#pragma unroll
    for (int i = 0; i < 32; i++) {
        float x1 = src[2 * i], x2 = src[2 * i + 1];
        float c = cosd[b * 32 + i], s = sind[b * 32 + i];
        dst[2 * i]     = x1 * c - x2 * s;
        dst[2 * i + 1] = x2 * c + x1 * s;
    }
}

// =====================================================================
// scores (tf32 MMA, double-buffered): Q[64h x 576] @ Keys[128tok x 576]^T
// =====================================================================
__global__ __launch_bounds__(256) void mma_scores(
    const float* __restrict__ qeff,
    const float* __restrict__ kvlat,
    const float* __restrict__ kpe,
    const float* __restrict__ cache_kv,
    const float* __restrict__ cache_pe,
    const int* __restrict__ block_table,
    const int* __restrict__ slot_mapping,
    float* __restrict__ scores)
{
    const int nt = blockIdx.x, mt = blockIdx.y, b = blockIdx.z;
    __shared__ unsigned As[2][64][20];    // [m][k]
    __shared__ unsigned Bs[2][16][132];   // [k][n]
    const int t = threadIdx.x, lane = t & 31, wid = t >> 5;
    const int warp_m = wid >> 1, warp_n = wid & 1;
    const int lq = lane >> 2, lr = lane & 3;

    const int blkid = block_table[b * 16 + nt];
    const int slotm = slot_mapping[b];
    const int ovr = ((slotm >> 7) == blkid) ? (slotm & 127) : -1;

    const float* Ab = qeff + (long)b * 73728 + (long)(mt * 64) * 576;
    const float* kvb = cache_kv + (long)blkid * 65536;
    const float* peb = cache_pe + (long)blkid * 8192;

    const int am = t >> 2, akq = (t & 3) * 4;
    const int bn0 = t >> 2, bkq0 = (t & 3) * 4;
    const int bn1 = (t + 256) >> 2, bkq1 = bkq0;

    // fetch lambda-ish (manual): B element for token n, k offset kq (float4)
    auto fetchB = [&](int n, int kq) -> float4 {
        if (kq < 512) {
            return (n == ovr)
                ? *reinterpret_cast<const float4*>(&kvlat[b * 512 + kq])
                : *reinterpret_cast<const float4*>(&kvb[(long)n * 512 + kq]);
        } else {
            return (n == ovr)
                ? *reinterpret_cast<const float4*>(&kpe[b * 64 + (kq - 512)])
                : *reinterpret_cast<const float4*>(&peb[(long)n * 64 + (kq - 512)]);
        }
    };

    float4 fa, fb0, fb1;
    fa  = *reinterpret_cast<const float4*>(&Ab[(long)am * 576 + akq]);
    fb0 = fetchB(bn0, bkq0);
    fb1 = fetchB(bn1, bkq1);
    *reinterpret_cast<uint4*>(&As[0][am][akq]) =
        make_uint4(f2tf(fa.x), f2tf(fa.y), f2tf(fa.z), f2tf(fa.w));
    Bs[0][bkq0 + 0][bn0] = f2tf(fb0.x); Bs[0][bkq0 + 1][bn0] = f2tf(fb0.y);
    Bs[0][bkq0 + 2][bn0] = f2tf(fb0.z); Bs[0][bkq0 + 3][bn0] = f2tf(fb0.w);
    Bs[0][bkq1 + 0][bn1] = f2tf(fb1.x); Bs[0][bkq1 + 1][bn1] = f2tf(fb1.y);
    Bs[0][bkq1 + 2][bn1] = f2tf(fb1.z); Bs[0][bkq1 + 3][bn1] = f2tf(fb1.w);
    __syncthreads();

    float acc[8][4];
#pragma unroll
    for (int i = 0; i < 8; i++)
#pragma unroll
        for (int j = 0; j < 4; j++) acc[i][j] = 0.f;

    const int nIter = 576 / 16;  // 36
    for (int it = 0; it < nIter; it++) {
        const int cur = it & 1, nxt = cur ^ 1;
        const bool hasNext = (it + 1 < nIter);
        if (hasNext) {
            int kn = (it + 1) * 16;
            fa  = *reinterpret_cast<const float4*>(&Ab[(long)am * 576 + kn + akq]);
            fb0 = fetchB(bn0, kn + bkq0);
            fb1 = fetchB(bn1, kn + bkq1);
        }
#pragma unroll
        for (int kk = 0; kk < 16; kk += 8) {
            int ar = warp_m * 16 + lq;
            int ak = kk + lr;
            unsigned a0 = As[cur][ar][ak], a1 = As[cur][ar + 8][ak];
            unsigned a2 = As[cur][ar][ak + 4], a3 = As[cur][ar + 8][ak + 4];
#pragma unroll
            for (int nt8 = 0; nt8 < 8; nt8++) {
                int bn = warp_n * 64 + nt8 * 8 + lq;
                unsigned b0 = Bs[cur][kk + lr][bn];
                unsigned b1 = Bs[cur][kk + 4 + lr][bn];
                mma_tf32(acc[nt8], a0, a1, a2, a3, b0, b1);
            }
        }
        if (hasNext) {
            *reinterpret_cast<uint4*>(&As[nxt][am][akq]) =
                make_uint4(f2tf(fa.x), f2tf(fa.y), f2tf(fa.z), f2tf(fa.w));
            Bs[nxt][bkq0 + 0][bn0] = f2tf(fb0.x); Bs[nxt][bkq0 + 1][bn0] = f2tf(fb0.y);
            Bs[nxt][bkq0 + 2][bn0] = f2tf(fb0.z); Bs[nxt][bkq0 + 3][bn0] = f2tf(fb0.w);
            Bs[nxt][bkq1 + 0][bn1] = f2tf(fb1.x); Bs[nxt][bkq1 + 1][bn1] = f2tf(fb1.y);
            Bs[nxt][bkq1 + 2][bn1] = f2tf(fb1.z); Bs[nxt][bkq1 + 3][bn1] = f2tf(fb1.w);
        }
        __syncthreads();
    }
    const long row0 = (long)(b * 128 + mt * 64 + warp_m * 16 + lq);
#pragma unroll
    for (int nt8 = 0; nt8 < 8; nt8++) {
        int col = nt * 128 + warp_n * 64 + nt8 * 8 + 2 * lr;
        *reinterpret_cast<float2*>(&scores[row0 * 2048 + col]) =
            make_float2(acc[nt8][0] * SCALEF, acc[nt8][1] * SCALEF);
        *reinterpret_cast<float2*>(&scores[(row0 + 8) * 2048 + col]) =
            make_float2(acc[nt8][2] * SCALEF, acc[nt8][3] * SCALEF);
    }
}

// ---------------- softmax ----------------
__global__ void softmax_kernel(float* __restrict__ scores,
                               const int* __restrict__ seq_lens) {
    const int row = blockIdx.x;
    const int b = row >> 7;
    const int L = seq_lens[b];
    float* p = scores + (long)row * 2048;
    const int t = threadIdx.x;
    __shared__ float sd[256];

    float m = -1e30f;
    for (int s = t; s < 2048; s += 256)
        if (s < L) m = fmaxf(m, p[s]);
    sd[t] = m; __syncthreads();
    for (int o = 128; o > 0; o >>= 1) { if (t < o) sd[t] = fmaxf(sd[t], sd[t + o]); __syncthreads(); }
    m = sd[0]; __syncthreads();

    float sum = 0.f;
    for (int s = t; s < 2048; s += 256) {
        float e = (s < L) ? __expf(p[s] - m) : 0.f;
        p[s] = e;
        sum += e;
    }
    sd[t] = sum; __syncthreads();
    for (int o = 128; o > 0; o >>= 1) { if (t < o) sd[t] += sd[t + o]; __syncthreads(); }
    float inv = 1.f / sd[0];
    for (int s = t; s < 2048; s += 256) p[s] *= inv;
}

// =====================================================================
// ctx (tf32 MMA, double-buffered): attn[64h x 2048] @ V[2048 x 128cols]
// =====================================================================
__global__ __launch_bounds__(256) void mma_ctx(
    const float* __restrict__ scores,
    const float* __restrict__ kvlat,
    const float* __restrict__ cache_kv,
    const int* __restrict__ block_table,
    const int* __restrict__ slot_mapping,
    float* __restrict__ ctx)
{
    const int nt = blockIdx.x, mt = blockIdx.y, b = blockIdx.z;
    __shared__ unsigned As[2][64][20];
    __shared__ unsigned Bs[2][16][132];
    const int t = threadIdx.x, lane = t & 31, wid = t >> 5;
    const int warp_m = wid >> 1, warp_n = wid & 1;
    const int lq = lane >> 2, lr = lane & 3;
    const int slotm = slot_mapping[b];
    const int ovrBlk = slotm >> 7, ovrOff = slotm & 127;

    const int am = t >> 2, akq = (t & 3) * 4;
    const int bkk0 = t >> 5, bn0 = (t & 31) * 4;
    const int bkk1 = (t + 256) >> 5, bn1 = bn0;

    auto fetchB = [&](int k0, int kk, int n0) -> float4 {
        int blkid = block_table[b * 16 + ((k0 + kk) >> 7)];
        int soff = (k0 + kk) & 127;
        if (blkid == ovrBlk && soff == ovrOff)
            return *reinterpret_cast<const float4*>(&kvlat[b * 512 + nt * 128 + n0]);
        return *reinterpret_cast<const float4*>(
            &cache_kv[(long)(blkid * 128 + soff) * 512 + nt * 128 + n0]);
    };

    const long arow = (long)(b * 128 + mt * 64 + am);
    float4 fa, fb0, fb1;
    fa  = *reinterpret_cast<const float4*>(&scores[arow * 2048 + akq]);
    fb0 = fetchB(0, bkk0, bn0);
    fb1 = fetchB(0, bkk1, bn1);
    *reinterpret_cast<uint4*>(&As[0][am][akq]) =
        make_uint4(f2tf(fa.x), f2tf(fa.y), f2tf(fa.z), f2tf(fa.w));
    *reinterpret_cast<uint4*>(&Bs[0][bkk0][bn0]) =
        make_uint4(f2tf(fb0.x), f2tf(fb0.y), f2tf(fb0.z), f2tf(fb0.w));
    *reinterpret_cast<uint4*>(&Bs[0][bkk1][bn1]) =
        make_uint4(f2tf(fb1.x), f2tf(fb1.y), f2tf(fb1.z), f2tf(fb1.w));
    __syncthreads();

    float acc[8][4];
#pragma unroll
    for (int i = 0; i < 8; i++)
#pragma unroll
        for (int j = 0; j < 4; j++) acc[i][j] = 0.f;

    const int nIter = 2048 / 16;  // 128
    for (int it = 0; it < nIter; it++) {
        const int cur = it & 1, nxt = cur ^ 1;
        const bool hasNext = (it + 1 < nIter);
        if (hasNext) {
            int kn = (it + 1) * 16;
            fa  = *reinterpret_cast<const float4*>(&scores[arow * 2048 + kn + akq]);
            fb0 = fetchB(kn, bkk0, bn0);
            fb1 = fetchB(kn, bkk1, bn1);
        }
#pragma unroll
        for (int kk = 0; kk < 16; kk += 8) {
            int ar = warp_m * 16 + lq;
            int ak = kk + lr;
            unsigned a0 = As[cur][ar][ak], a1 = As[cur][ar + 8][ak];
            unsigned a2 = As[cur][ar][ak + 4], a3 = As[cur][ar + 8][ak + 4];
#pragma unroll
            for (int nt8 = 0; nt8 < 8; nt8++) {
                int bn = warp_n * 64 + nt8 * 8 + lq;
                unsigned b0 = Bs[cur][kk + lr][bn];
                unsigned b1 = Bs[cur][kk + 4 + lr][bn];
                mma_tf32(acc[nt8], a0, a1, a2, a3, b0, b1);
            }
        }
        if (hasNext) {
            *reinterpret_cast<uint4*>(&As[nxt][am][akq]) =
                make_uint4(f2tf(fa.x), f2tf(fa.y), f2tf(fa.z), f2tf(fa.w));
            *reinterpret_cast<uint4*>(&Bs[nxt][bkk0][bn0]) =
                make_uint4(f2tf(fb0.x), f2tf(fb0.y), f2tf(fb0.z), f2tf(fb0.w));
            *reinterpret_cast<uint4*>(&Bs[nxt][bkk1][bn1]) =
                make_uint4(f2tf(fb1.x), f2tf(fb1.y), f2tf(fb1.z), f2tf(fb1.w));
        }
        __syncthreads();
    }
    const long row0 = (long)(b * 128 + mt * 64 + warp_m * 16 + lq);
#pragma unroll
    for (int nt8 = 0; nt8 < 8; nt8++) {
        int col = nt * 128 + warp_n * 64 + nt8 * 8 + 2 * lr;
        *reinterpret_cast<float2*>(&ctx[row0 * 512 + col]) =
            make_float2(acc[nt8][0], acc[nt8][1]);
        *reinterpret_cast<float2*>(&ctx[(row0 + 8) * 512 + col]) =
            make_float2(acc[nt8][2], acc[nt8][3]);
    }
}

// ------------------------------ host driver ------------------------------
extern "C" void kernel_launch(void* const* d_in, const int* in_sizes, int n_in,
                              void* d_out, int out_size) {
    const float* hidden    = (const float*)d_in[0];
    const float* cosd      = (const float*)d_in[1];
    const float* sind      = (const float*)d_in[2];
    const float* Wq_a      = (const float*)d_in[3];
    const float* q_ln_w    = (const float*)d_in[4];
    const float* Wq_b      = (const float*)d_in[5];
    const float* Wkv_a     = (const float*)d_in[6];
    const float* kv_ln_w   = (const float*)d_in[7];
    const float* Wukt      = (const float*)d_in[8];
    const float* Wuv       = (const float*)d_in[9];
    const float* Wo        = (const float*)d_in[10];
    const float* cache_kv  = (const float*)d_in[11];
    const float* cache_pe  = (const float*)d_in[12];
    const int*   block_tab = (const int*)d_in[13];
    const int*   slot_map  = (const int*)d_in[14];
    const int*   seq_lens  = (const int*)d_in[15];
    float* out = (float*)d_out;

    float *qa, *kvb, *kvlat, *kpe, *q, *qeff, *scores, *ctx, *headout, *part;
    cudaGetSymbolAddress((void**)&qa,      g_qa);
    cudaGetSymbolAddress((void**)&kvb,     g_kv);
    cudaGetSymbolAddress((void**)&kvlat,   g_kvlat);
    cudaGetSymbolAddress((void**)&kpe,     g_kpe);
    cudaGetSymbolAddress((void**)&q,       g_q);
    cudaGetSymbolAddress((void**)&qeff,    g_qeff);
    cudaGetSymbolAddress((void**)&scores,  g_scores);
    cudaGetSymbolAddress((void**)&ctx,     g_ctx);
    cudaGetSymbolAddress((void**)&headout, g_headout);
    cudaGetSymbolAddress((void**)&part,    g_part);

    // 1) q_a = hidden @ Wq_a  (K=5120, N=1536), splitK 16 x 320
    mma_gemm32<<<dim3(12, 16, 1), 256>>>(hidden, 5120, 0, Wq_a, 1536, 0,
                                         part, 1536, 0, 49152, 5120, 1536, 320);
    reduce_kernel<<<(49152 + 255) / 256, 256>>>(qa, part, 16, 49152, 49152);

    // 2) kv = hidden @ Wkv_a  (K=5120, N=576), splitK 16 x 320
    mma_gemm32<<<dim3(5, 16, 1), 256>>>(hidden, 5120, 0, Wkv_a, 576, 0,
                                        part, 576, 0, 18432, 5120, 576, 320);
    reduce_kernel<<<(18432 + 255) / 256, 256>>>(kvb, part, 16, 18432, 18432);

    // 3) norms + k_pe rope
    norm_rope_kernel<<<32, 256>>>(qa, kvb, kvlat, kpe, q_ln_w, kv_ln_w, cosd, sind);

    // 4) q = q_a_norm @ Wq_b  (K=1536, N=24576), splitK 2 x 768
    mma_gemm32<<<dim3(192, 2, 1), 256>>>(qa, 1536, 0, Wq_b, 24576, 0,
                                         part, 24576, 0, 786432, 1536, 24576, 768);
    reduce_kernel<<<(786432 + 255) / 256, 256>>>(q, part, 2, 786432, 786432);

    // 5) rope q_pe -> qeff[..., 512:576]
    qpe_rope_kernel<<<16, 256>>>(q, cosd, sind, qeff);

    // 6) q_lat[b,h,:512] = q_nope[b,h] @ W_UK_T[h]  (per-head, fp32)
    smallgemm8<128><<<dim3(4, 1, 128), 128>>>(q, 24576, 192, Wukt, 512, 65536,
                                              qeff, 73728, 576, 0, 128, 512, 128);

    // 7) attention scores (tf32 MMA, 1024 blocks)
    mma_scores<<<dim3(16, 2, 32), 256>>>(qeff, kvlat, kpe, cache_kv, cache_pe,
                                         block_tab, slot_map, scores);

    // 8) softmax
    softmax_kernel<<<4096, 256>>>(scores, seq_lens);

    // 9) ctx = attn @ keys_kv (tf32 MMA, 256 blocks)
    mma_ctx<<<dim3(4, 2, 32), 256>>>(scores, kvlat, cache_kv, block_tab,
                                     slot_map, ctx);

    // 10) headout = ctx @ W_UV (per-head, fp32), splitK 4
    smallgemm8<128><<<dim3(1, 4, 128), 128>>>(ctx, 65536, 512, Wuv, 128, 65536,
                                              part, 16384, 128, 524288, 512, 128, 128);
    reduce_kernel<<<(524288 + 255) / 256, 256>>>(headout, part, 4, 524288, 524288);

    // 11) out = headout @ Wo  (K=16384, N=5120), splitK 8 x 2048
    mma_gemm32<<<dim3(40, 8, 1), 256>>>(headout, 16384, 0, Wo, 5120, 0,
                                        part, 5120, 0, 163840, 16384, 5120, 2048);
    reduce_kernel<<<(163840 + 255) / 256, 256>>>(out, part, 8, 163840, 163840);
}